// round 1
// baseline (speedup 1.0000x reference)
#include <cuda_runtime.h>
#include <math.h>

#define BB 32
#define HH 1024
#define WW 1024
#define RAD 15            // kernel 31, radius 15
#define KK2 961.0f        // 31*31
#define SMOOTH 0.001f

// Scratch: horizontal box-sums of target (128 MB), per-batch accumulators.
__device__ float g_hsum[(size_t)BB * HH * WW];
__device__ float g_inter[BB];
__device__ float g_mask[BB];

// ---------------------------------------------------------------------------
// Kernel 0: zero the per-batch accumulators (graph replays must be idempotent)
// ---------------------------------------------------------------------------
__global__ void k_zero() {
    int i = threadIdx.x;
    if (i < BB) { g_inter[i] = 0.0f; g_mask[i] = 0.0f; }
}

// ---------------------------------------------------------------------------
// Kernel 1: horizontal 31-tap box SUM of target, zero padding.
// One block per image row (32*1024 blocks). Row staged in shared memory;
// each of 256 threads produces 4 consecutive outputs with a sliding window.
// ---------------------------------------------------------------------------
__global__ __launch_bounds__(256) void k_hpass(const float* __restrict__ target) {
    __shared__ float row[WW];
    const int rowIdx = blockIdx.x;                 // b*HH + y
    const float* __restrict__ src = target + (size_t)rowIdx * WW;
    float* __restrict__ dst = g_hsum + (size_t)rowIdx * WW;

    // coalesced row load
    for (int i = threadIdx.x; i < WW; i += 256) row[i] = src[i];
    __syncthreads();

    const int c0 = threadIdx.x * 4;
    float s = 0.0f;
    #pragma unroll
    for (int j = -RAD; j <= RAD; j++) {
        int idx = c0 + j;
        if (idx >= 0 && idx < WW) s += row[idx];
    }
    dst[c0] = s;
    #pragma unroll
    for (int k = 1; k < 4; k++) {
        int c = c0 + k;
        int ai = c + RAD;          // incoming
        int si = c - RAD - 1;      // outgoing
        if (ai < WW) s += row[ai];
        if (si >= 0) s -= row[si];
        dst[c] = s;
    }
}

// ---------------------------------------------------------------------------
// Kernel 2 (fused): vertical 31-tap box sum over g_hsum with a shared-memory
// ring buffer (each hsum element read from DRAM exactly once), fused with
// sigmoid(output), weight, and per-batch Dice partial reductions.
// Grid: (ySegments=8, colTiles=8, batches=32), 128 threads (one per column).
// ---------------------------------------------------------------------------
#define TCOLS 128
#define YSEG  128

__global__ __launch_bounds__(128) void k_vpass(const float* __restrict__ output,
                                               const float* __restrict__ target) {
    __shared__ float ring[32][TCOLS];   // 16 KB ring of recent hsum rows
    __shared__ float red_i[4], red_m[4];

    const int tid = threadIdx.x;
    const int b  = blockIdx.z;
    const int x  = blockIdx.y * TCOLS + tid;
    const int y0 = blockIdx.x * YSEG;

    const float* __restrict__ hs  = g_hsum + (size_t)b * HH * WW;
    const size_t base = (size_t)b * HH * WW;

    // Preload rows [y0-15, y0+14] into the running sum + ring (zero pad).
    float running = 0.0f;
    for (int r = y0 - RAD; r < y0 + RAD; r++) {
        float v = (r >= 0 && r < HH) ? hs[(size_t)r * WW + x] : 0.0f;
        ring[r & 31][tid] = v;
        running += v;
    }

    float li = 0.0f, lm = 0.0f;
    for (int y = y0; y < y0 + YSEG; y++) {
        const int ra = y + RAD;
        float va = (ra < HH) ? hs[(size_t)ra * WW + x] : 0.0f;
        running += va;
        if (y > y0) {
            const int rs = y - RAD - 1;
            float vs = (rs >= 0) ? ring[rs & 31][tid] : 0.0f;
            running -= vs;
        }
        ring[ra & 31][tid] = va;   // slots rs..ra span exactly 32 rows

        const float avg = running * (1.0f / KK2);
        const size_t idx = base + (size_t)y * WW + x;
        const float t = target[idx];
        const float o = 1.0f / (1.0f + __expf(-output[idx]));
        const float w = 1.0f + 5.0f * fabsf(avg - t);
        li += o * t * w;
        lm += (t + o) * w;
    }

    // Block reduction (4 warps) then atomic into per-batch accumulators.
    #pragma unroll
    for (int off = 16; off > 0; off >>= 1) {
        li += __shfl_down_sync(0xFFFFFFFFu, li, off);
        lm += __shfl_down_sync(0xFFFFFFFFu, lm, off);
    }
    const int warp = tid >> 5, lane = tid & 31;
    if (lane == 0) { red_i[warp] = li; red_m[warp] = lm; }
    __syncthreads();
    if (tid == 0) {
        float si = red_i[0] + red_i[1] + red_i[2] + red_i[3];
        float sm = red_m[0] + red_m[1] + red_m[2] + red_m[3];
        atomicAdd(&g_inter[b], si);
        atomicAdd(&g_mask[b], sm);
    }
}

// ---------------------------------------------------------------------------
// Kernel 3: final scalar loss = mean_b( 1 - (2*inter+s)/(mask+s) )
// ---------------------------------------------------------------------------
__global__ void k_final(float* __restrict__ out) {
    float l = 0.0f;
    if (threadIdx.x < BB) {
        l = 1.0f - (2.0f * g_inter[threadIdx.x] + SMOOTH) /
                   (g_mask[threadIdx.x] + SMOOTH);
    }
    #pragma unroll
    for (int off = 16; off > 0; off >>= 1)
        l += __shfl_down_sync(0xFFFFFFFFu, l, off);
    if (threadIdx.x == 0) out[0] = l * (1.0f / (float)BB);
}

// ---------------------------------------------------------------------------
extern "C" void kernel_launch(void* const* d_in, const int* in_sizes, int n_in,
                              void* d_out, int out_size) {
    const float* output = (const float*)d_in[0];   // metadata order: output, target
    const float* target = (const float*)d_in[1];
    float* out = (float*)d_out;

    k_zero<<<1, 32>>>();
    k_hpass<<<BB * HH, 256>>>(target);
    dim3 grid(HH / YSEG, WW / TCOLS, BB);          // (8, 8, 32)
    k_vpass<<<grid, TCOLS>>>(output, target);
    k_final<<<1, 32>>>(out);
}

// round 2
// speedup vs baseline: 1.0271x; 1.0271x over previous
#include <cuda_runtime.h>
#include <math.h>

#define BB 32
#define HH 1024
#define WW 1024
#define RAD 15            // kernel 31, radius 15
#define KK2 961.0f        // 31*31
#define SMOOTH 0.001f

#define YSEG   128
#define TCOLS  256        // columns per vloss block (2 per thread, 128 threads)
#define VBLOCKS (HH / YSEG * (WW / TCOLS) * BB)   // 8*4*32 = 1024

// Scratch: horizontal box-sums of target (128 MB), per-batch accumulators.
__device__ float g_hsum[(size_t)BB * HH * WW];
__device__ float g_inter[BB];
__device__ float g_mask[BB];
__device__ int   g_done = 0;

// ---------------------------------------------------------------------------
// Kernel 1: horizontal 31-tap box SUM of target, zero padding.
// One block per image row. Row staged in shared via float4; each of 256
// threads produces 4 consecutive outputs and stores them as ONE float4
// (coalesced STG.128 — the previous version's stride-4 scalar stores caused
// 4x L2 sector amplification).
// Block 0 also zeroes the per-batch accumulators (runs before k_vloss).
// ---------------------------------------------------------------------------
__global__ __launch_bounds__(256) void k_hpass(const float* __restrict__ target) {
    __shared__ float row[WW];
    const int rowIdx = blockIdx.x;                 // b*HH + y

    if (rowIdx == 0 && threadIdx.x < BB) {
        g_inter[threadIdx.x] = 0.0f;
        g_mask[threadIdx.x]  = 0.0f;
    }

    const float4* __restrict__ src4 =
        (const float4*)(target + (size_t)rowIdx * WW);
    // one float4 load per thread covers the row
    ((float4*)row)[threadIdx.x] = src4[threadIdx.x];
    __syncthreads();

    const int c0 = threadIdx.x * 4;
    float out0, out1, out2, out3;
    float s = 0.0f;
    #pragma unroll
    for (int j = -RAD; j <= RAD; j++) {
        int idx = c0 + j;
        if (idx >= 0 && idx < WW) s += row[idx];
    }
    out0 = s;
    {   int ai = c0 + 1 + RAD, si = c0 - RAD;
        if (ai < WW) s += row[ai];
        if (si >= 0) s -= row[si];
        out1 = s; }
    {   int ai = c0 + 2 + RAD, si = c0 + 1 - RAD;
        if (ai < WW) s += row[ai];
        if (si >= 0) s -= row[si];
        out2 = s; }
    {   int ai = c0 + 3 + RAD, si = c0 + 2 - RAD;
        if (ai < WW) s += row[ai];
        if (si >= 0) s -= row[si];
        out3 = s; }

    ((float4*)(g_hsum + (size_t)rowIdx * WW))[threadIdx.x] =
        make_float4(out0, out1, out2, out3);
}

// ---------------------------------------------------------------------------
// Kernel 2 (fused): vertical 31-tap box sum over g_hsum with a shared-memory
// ring buffer (each hsum element read from DRAM exactly once), fused with
// sigmoid(output), weight, per-batch Dice reduction, AND the final scalar
// loss (computed by the last block to finish, via g_done counter).
// Each thread owns 2 adjacent columns (float2 on all three streams).
// Grid: (8, 4, 32) = 1024 blocks, 128 threads.
// ---------------------------------------------------------------------------
__global__ __launch_bounds__(128) void k_vloss(const float* __restrict__ output,
                                               const float* __restrict__ target,
                                               float* __restrict__ lossOut) {
    __shared__ float2 ring[32][128];   // 32 KB ring of recent hsum rows
    __shared__ float red_i[4], red_m[4];
    __shared__ bool  isLast;

    const int tid = threadIdx.x;
    const int b   = blockIdx.z;
    const int xi  = blockIdx.y * (TCOLS / 2) + tid;   // float2 column index
    const int y0  = blockIdx.x * YSEG;

    const float2* __restrict__ hs2 =
        (const float2*)g_hsum + (size_t)b * HH * (WW / 2);
    const float2* __restrict__ tg2 =
        (const float2*)target + (size_t)b * HH * (WW / 2);
    const float2* __restrict__ op2 =
        (const float2*)output + (size_t)b * HH * (WW / 2);

    // Preload rows [y0-15, y0+14] into the running sum + ring (zero pad).
    float rx = 0.0f, ry = 0.0f;
    for (int r = y0 - RAD; r < y0 + RAD; r++) {
        float2 v = (r >= 0) ? hs2[(size_t)r * (WW / 2) + xi]
                            : make_float2(0.0f, 0.0f);
        ring[r & 31][tid] = v;
        rx += v.x; ry += v.y;
    }

    float li = 0.0f, lm = 0.0f;
    #pragma unroll 4
    for (int y = y0; y < y0 + YSEG; y++) {
        const int ra = y + RAD;
        float2 va = (ra < HH) ? hs2[(size_t)ra * (WW / 2) + xi]
                              : make_float2(0.0f, 0.0f);
        rx += va.x; ry += va.y;
        if (y > y0) {
            const int rs = y - RAD - 1;
            float2 vs = (rs >= 0) ? ring[rs & 31][tid]
                                  : make_float2(0.0f, 0.0f);
            rx -= vs.x; ry -= vs.y;
        }
        ring[ra & 31][tid] = va;

        const size_t idx = (size_t)y * (WW / 2) + xi;
        const float2 t = tg2[idx];
        const float2 o = op2[idx];
        const float ox = 1.0f / (1.0f + __expf(-o.x));
        const float oy = 1.0f / (1.0f + __expf(-o.y));
        const float wx = 1.0f + 5.0f * fabsf(rx * (1.0f / KK2) - t.x);
        const float wy = 1.0f + 5.0f * fabsf(ry * (1.0f / KK2) - t.y);
        li += ox * t.x * wx + oy * t.y * wy;
        lm += (t.x + ox) * wx + (t.y + oy) * wy;
    }

    // Block reduction (4 warps) then atomic into per-batch accumulators.
    #pragma unroll
    for (int off = 16; off > 0; off >>= 1) {
        li += __shfl_down_sync(0xFFFFFFFFu, li, off);
        lm += __shfl_down_sync(0xFFFFFFFFu, lm, off);
    }
    const int warp = tid >> 5, lane = tid & 31;
    if (lane == 0) { red_i[warp] = li; red_m[warp] = lm; }
    __syncthreads();
    if (tid == 0) {
        float si = red_i[0] + red_i[1] + red_i[2] + red_i[3];
        float sm = red_m[0] + red_m[1] + red_m[2] + red_m[3];
        atomicAdd(&g_inter[b], si);
        atomicAdd(&g_mask[b], sm);
        __threadfence();
        int c = atomicAdd(&g_done, 1);
        isLast = (c == VBLOCKS - 1);
    }
    __syncthreads();

    // Last block computes the scalar loss and resets g_done for graph replay.
    if (isLast && tid == 0) {
        float l = 0.0f;
        #pragma unroll
        for (int k = 0; k < BB; k++) {
            l += 1.0f - (2.0f * g_inter[k] + SMOOTH) / (g_mask[k] + SMOOTH);
        }
        lossOut[0] = l * (1.0f / (float)BB);
        g_done = 0;
    }
}

// ---------------------------------------------------------------------------
extern "C" void kernel_launch(void* const* d_in, const int* in_sizes, int n_in,
                              void* d_out, int out_size) {
    const float* output = (const float*)d_in[0];   // metadata order: output, target
    const float* target = (const float*)d_in[1];
    float* out = (float*)d_out;

    k_hpass<<<BB * HH, 256>>>(target);
    dim3 grid(HH / YSEG, WW / TCOLS, BB);          // (8, 4, 32)
    k_vloss<<<grid, 128>>>(output, target, out);
}

// round 5
// speedup vs baseline: 2.6764x; 2.6058x over previous
#include <cuda_runtime.h>
#include <cuda_fp16.h>
#include <math.h>

#define BB 32
#define HH 1024
#define WW 1024
#define RAD 15            // kernel 31, radius 15
#define INV_K2 (1.0f/961.0f)
#define SMOOTH 0.001f

#define VSEG 64                        // rows per k_vpass block
#define ROWS_PER_HBLK 16               // rows per k_hloss block
#define HBLOCKS (BB * HH / ROWS_PER_HBLK)   // 2048

// Scratch: vertical box-sums of target in fp16 (64 MB), per-batch accumulators.
__device__ __half g_vsum[(size_t)BB * HH * WW];
__device__ float  g_inter[BB];
__device__ float  g_mask[BB];
__device__ int    g_done = 0;

// ---------------------------------------------------------------------------
// Kernel 1: vertical 31-tap box SUM of target (zero padding), fp16 output.
// No shared memory. Thread owns 4 columns (float4); running sums in regs;
// the outgoing row is re-loaded from global (L2 hit, read 31 iters earlier).
// Grid: (HH/VSEG, BB) = (16, 32), 256 threads (256*4 = full row width).
// Block (0,0) also zeroes the per-batch accumulators.
// ---------------------------------------------------------------------------
__global__ __launch_bounds__(256) void k_vpass(const float* __restrict__ target) {
    const int b  = blockIdx.y;
    const int y0 = blockIdx.x * VSEG;
    const int x4 = threadIdx.x;                     // float4 / uint2 column index

    if (blockIdx.x == 0 && b == 0 && threadIdx.x < BB) {
        g_inter[threadIdx.x] = 0.0f;
        g_mask[threadIdx.x]  = 0.0f;
    }

    const float4* __restrict__ t4 =
        (const float4*)(target + (size_t)b * HH * WW);
    uint2* __restrict__ vrow =
        (uint2*)(g_vsum + (size_t)b * HH * WW);

    float s0 = 0.f, s1 = 0.f, s2 = 0.f, s3 = 0.f;

    // Preload rows [y0-15, y0+14]
    #pragma unroll 4
    for (int r = y0 - RAD; r < y0 + RAD; r++) {
        if (r >= 0 && r < HH) {
            float4 v = t4[(size_t)r * (WW/4) + x4];
            s0 += v.x; s1 += v.y; s2 += v.z; s3 += v.w;
        }
    }

    #pragma unroll 4
    for (int y = y0; y < y0 + VSEG; y++) {
        const int ra = y + RAD;
        if (ra < HH) {
            float4 v = t4[(size_t)ra * (WW/4) + x4];
            s0 += v.x; s1 += v.y; s2 += v.z; s3 += v.w;
        }
        // Subtract the outgoing row ONLY once it has actually been added:
        // at y == y0 the sum is exactly rows [y0-15, y0+15]; row y0-16 was
        // never included (R4 BUG: unconditional subtract corrupted 15/16 of
        // the y-segments by one full row).
        if (y > y0) {
            const int rs = y - RAD - 1;
            if (rs >= 0) {                           // L2 hit (read 31 rows ago)
                float4 v = t4[(size_t)rs * (WW/4) + x4];
                s0 -= v.x; s1 -= v.y; s2 -= v.z; s3 -= v.w;
            }
        }
        __half2 h01 = __floats2half2_rn(s0, s1);
        __half2 h23 = __floats2half2_rn(s2, s3);
        uint2 pk;
        pk.x = *(const unsigned int*)&h01;
        pk.y = *(const unsigned int*)&h23;
        vrow[(size_t)y * (WW/4) + x4] = pk;          // 8B/thread, coalesced
    }
}

// ---------------------------------------------------------------------------
// Kernel 2 (fused): horizontal 31-tap sum over g_vsum + sigmoid + weight +
// per-batch Dice reduction + final scalar (last block via done-counter).
// NO shared memory for data: each thread owns 8 consecutive columns and
// loads its 40-wide fp16 window (5 aligned uint4) straight from global
// (halo served by L1/L2). Sliding sum entirely in registers.
// Grid: 2048 blocks x 256 threads; block = 16 rows of one batch image.
// ---------------------------------------------------------------------------
__global__ __launch_bounds__(256) void k_hloss(const float* __restrict__ output,
                                               const float* __restrict__ target,
                                               float* __restrict__ lossOut) {
    const int tid  = threadIdx.x;
    const int t    = tid & 127;          // column group: cols [8t, 8t+7]
    const int rsub = tid >> 7;           // 0/1: which of the 2 rows per iter
    const int rowBase = blockIdx.x * ROWS_PER_HBLK;     // global row index
    const int b  = rowBase >> 10;                       // batch (no crossing)
    const int y0 = rowBase & (HH - 1);

    const __half* __restrict__ vs = g_vsum + (size_t)b * HH * WW;
    const float*  __restrict__ tg = target + (size_t)b * HH * WW;
    const float*  __restrict__ op = output + (size_t)b * HH * WW;

    const int c0 = 8 * t - 16;           // local window base (col of v[0])
    float li = 0.0f, lm = 0.0f;

    #pragma unroll
    for (int it = 0; it < ROWS_PER_HBLK / 2; it++) {
        const int y = y0 + it * 2 + rsub;

        // ---- load 40-value fp16 window: 5 aligned uint4, bounds as zeros
        const uint4* __restrict__ vrow = (const uint4*)(vs + (size_t)y * WW);
        float v[40];
        #pragma unroll
        for (int k = 0; k < 5; k++) {
            const int cb = c0 + 8 * k;
            float2 f01, f23, f45, f67;
            if (cb >= 0 && cb < WW) {
                uint4 u = vrow[cb >> 3];
                f01 = __half22float2(*(const __half2*)&u.x);
                f23 = __half22float2(*(const __half2*)&u.y);
                f45 = __half22float2(*(const __half2*)&u.z);
                f67 = __half22float2(*(const __half2*)&u.w);
            } else {
                f01 = f23 = f45 = f67 = make_float2(0.f, 0.f);
            }
            v[8*k+0] = f01.x; v[8*k+1] = f01.y;
            v[8*k+2] = f23.x; v[8*k+3] = f23.y;
            v[8*k+4] = f45.x; v[8*k+5] = f45.y;
            v[8*k+6] = f67.x; v[8*k+7] = f67.y;
        }

        // ---- initial 31-sum for col 8t: window cols [8t-15, 8t+15] = v[1..31]
        float s = 0.0f;
        #pragma unroll
        for (int j = 1; j <= 31; j++) s += v[j];

        // ---- target / output: 2 float4 each, perfectly coalesced
        const float4* __restrict__ trow = (const float4*)(tg + (size_t)y * WW);
        const float4* __restrict__ orow = (const float4*)(op + (size_t)y * WW);
        float4 ta = trow[2*t], tb = trow[2*t+1];
        float4 oa = orow[2*t], ob = orow[2*t+1];
        float tv[8] = {ta.x, ta.y, ta.z, ta.w, tb.x, tb.y, tb.z, tb.w};
        float ov[8] = {oa.x, oa.y, oa.z, oa.w, ob.x, ob.y, ob.z, ob.w};

        #pragma unroll
        for (int k = 0; k < 8; k++) {
            if (k) s += v[31 + k] - v[k];            // slide window
            const float avg = s * INV_K2;
            const float w   = 1.0f + 5.0f * fabsf(avg - tv[k]);
            const float sig = 1.0f / (1.0f + __expf(-ov[k]));
            li += sig * tv[k] * w;
            lm += (tv[k] + sig) * w;
        }
    }

    // ---- block reduction (8 warps) + per-batch atomics
    __shared__ float red_i[8], red_m[8];
    __shared__ bool  isLast;
    #pragma unroll
    for (int off = 16; off > 0; off >>= 1) {
        li += __shfl_down_sync(0xFFFFFFFFu, li, off);
        lm += __shfl_down_sync(0xFFFFFFFFu, lm, off);
    }
    const int warp = tid >> 5, lane = tid & 31;
    if (lane == 0) { red_i[warp] = li; red_m[warp] = lm; }
    __syncthreads();
    if (tid == 0) {
        float si = 0.f, sm = 0.f;
        #pragma unroll
        for (int w = 0; w < 8; w++) { si += red_i[w]; sm += red_m[w]; }
        atomicAdd(&g_inter[b], si);
        atomicAdd(&g_mask[b], sm);
        __threadfence();
        int c = atomicAdd(&g_done, 1);
        isLast = (c == HBLOCKS - 1);
    }
    __syncthreads();

    if (isLast && tid == 0) {
        __threadfence();
        float l = 0.0f;
        #pragma unroll
        for (int k = 0; k < BB; k++)
            l += 1.0f - (2.0f * g_inter[k] + SMOOTH) / (g_mask[k] + SMOOTH);
        lossOut[0] = l * (1.0f / (float)BB);
        g_done = 0;                                  // reset for graph replay
    }
}

// ---------------------------------------------------------------------------
extern "C" void kernel_launch(void* const* d_in, const int* in_sizes, int n_in,
                              void* d_out, int out_size) {
    const float* output = (const float*)d_in[0];   // metadata order: output, target
    const float* target = (const float*)d_in[1];
    float* out = (float*)d_out;

    dim3 vgrid(HH / VSEG, BB);                     // (16, 32)
    k_vpass<<<vgrid, 256>>>(target);
    k_hloss<<<HBLOCKS, 256>>>(output, target, out);
}